// round 2
// baseline (speedup 1.0000x reference)
#include <cuda_runtime.h>

// Problem dims
#define B_ 32
#define T_ 100
#define V_ 20000
#define E_ 128
#define H_ 128
#define M_ 64
#define DD_ 2
#define ROWS_X (B_*T_)          // 3200
#define ROWS_TOT (ROWS_X + B_)  // 3232 (x rows + a rows folded in)

// K1 GEMM config
#define TM 128
#define TN 128
#define TK 16
#define SPLIT 50
#define KC (V_/SPLIT)           // 400 (multiple of TK -> no k guards)
#define NKT (KC/TK)             // 25
#define NRT ((ROWS_TOT+TM-1)/TM)  // 26
#define NUNITS (NRT*SPLIT)      // 1300
#define GRID1 148

// Scratch (static device globals; no runtime allocation)
__device__ float g_parts[(size_t)SPLIT * ROWS_TOT * 128];  // ~83 MB partial sums
__device__ float g_P[(size_t)ROWS_X * 384];                // x_proj
__device__ float g_mask[ROWS_X];
__device__ float g_ae[B_ * E_];

__device__ __forceinline__ unsigned su32(const void* p) {
    return (unsigned)__cvta_generic_to_shared(p);
}
__device__ __forceinline__ void cpa16(unsigned dst, const void* src, int valid) {
    asm volatile("cp.async.ca.shared.global [%0], [%1], 16, %2;\n"
                 :: "r"(dst), "l"(src), "r"(valid ? 16 : 0));
}
__device__ __forceinline__ void cpcommit() { asm volatile("cp.async.commit_group;\n"); }
__device__ __forceinline__ void cpwait1()  { asm volatile("cp.async.wait_group 1;\n" ::: "memory"); }

// ---------------------------------------------------------------------------
// Kernel 1: partial GEMM  parts[s][m][n] = sum_{k in chunk s} A[m][k]*emb[k][n]
// A rows: m<3200 -> x row, 3200<=m<3232 -> a row. f32x2 packed FMA.
// ---------------------------------------------------------------------------
__global__ void __launch_bounds__(256, 1) k1_gemm(
    const float* __restrict__ x, const float* __restrict__ a,
    const float* __restrict__ emb)
{
    __shared__ float As[2][TM][TK + 4];   // [row][k], padded row (20 floats, 16B-aligned rows)
    __shared__ float Bs[2][TK][TN];       // [k][n]

    const int tid = threadIdx.x;
    const int tx = tid & 15;
    const int ty = tid >> 4;
    const unsigned AbufStride = sizeof(float) * TM * (TK + 4);
    const unsigned BbufStride = sizeof(float) * TK * TN;

    for (int u = blockIdx.x; u < NUNITS; u += GRID1) {
        const int rt = u % NRT;
        const int ks = u / NRT;
        const int m0 = rt * TM;
        const int k0 = ks * KC;

        // --- loader setup ---
        const float* arp[2]; int aval[2]; unsigned adst[2];
        #pragma unroll
        for (int j = 0; j < 2; j++) {
            int idx = tid + j * 256;       // 0..511
            int row = idx >> 2;            // 0..127
            int kq  = idx & 3;             // 0..3 (float4 within 16 k)
            int m = m0 + row;
            int v = (m < ROWS_TOT);
            const float* rp;
            if (m < ROWS_X)      rp = x + (size_t)m * V_;
            else if (v)          rp = a + (size_t)(m - ROWS_X) * V_;
            else                 rp = x;   // dummy, never copied (src-size 0)
            arp[j]  = rp + k0 + kq * 4;
            aval[j] = v;
            adst[j] = su32(&As[0][row][kq * 4]);
        }
        const float* brp[2]; unsigned bdst[2];
        #pragma unroll
        for (int j = 0; j < 2; j++) {
            int idx = tid + j * 256;
            int kr = idx >> 5;             // 0..15
            int nq = idx & 31;             // 0..31
            brp[j]  = emb + (size_t)(k0 + kr) * E_ + nq * 4;
            bdst[j] = su32(&Bs[0][kr][nq * 4]);
        }

        // accumulators: 8 rows x 4 col-pairs of f32x2
        unsigned long long acc[8][4];
        #pragma unroll
        for (int i = 0; i < 8; i++)
            #pragma unroll
            for (int p = 0; p < 4; p++) acc[i][p] = 0ULL;

        auto loadTile = [&](int t, int buf) {
            #pragma unroll
            for (int j = 0; j < 2; j++)
                cpa16(adst[j] + buf * AbufStride, arp[j] + (size_t)t * TK, aval[j]);
            #pragma unroll
            for (int j = 0; j < 2; j++)
                cpa16(bdst[j] + buf * BbufStride, brp[j] + (size_t)t * TK * E_, 1);
        };

        loadTile(0, 0);
        cpcommit();

        for (int t = 0; t < NKT; t++) {
            if (t + 1 < NKT) loadTile(t + 1, (t + 1) & 1);
            cpcommit();
            cpwait1();
            __syncthreads();
            const int buf = t & 1;
            #pragma unroll
            for (int k = 0; k < TK; k++) {
                unsigned long long ap[8];
                #pragma unroll
                for (int i = 0; i < 4; i++) {
                    float av = As[buf][ty * 4 + i][k];
                    asm("mov.b64 %0, {%1, %1};" : "=l"(ap[i]) : "f"(av));
                    float av2 = As[buf][64 + ty * 4 + i][k];
                    asm("mov.b64 %0, {%1, %1};" : "=l"(ap[4 + i]) : "f"(av2));
                }
                ulonglong2 b0 = *reinterpret_cast<const ulonglong2*>(&Bs[buf][k][tx * 4]);
                ulonglong2 b1 = *reinterpret_cast<const ulonglong2*>(&Bs[buf][k][64 + tx * 4]);
                unsigned long long bp0 = b0.x, bp1 = b0.y, bp2 = b1.x, bp3 = b1.y;
                #pragma unroll
                for (int i = 0; i < 8; i++) {
                    asm("fma.rn.f32x2 %0, %1, %2, %0;" : "+l"(acc[i][0]) : "l"(ap[i]), "l"(bp0));
                    asm("fma.rn.f32x2 %0, %1, %2, %0;" : "+l"(acc[i][1]) : "l"(ap[i]), "l"(bp1));
                    asm("fma.rn.f32x2 %0, %1, %2, %0;" : "+l"(acc[i][2]) : "l"(ap[i]), "l"(bp2));
                    asm("fma.rn.f32x2 %0, %1, %2, %0;" : "+l"(acc[i][3]) : "l"(ap[i]), "l"(bp3));
                }
            }
            __syncthreads();
        }

        // epilogue: write this (ks, row-tile) partial
        #pragma unroll
        for (int i = 0; i < 8; i++) {
            int row = (i < 4) ? (ty * 4 + i) : (64 + ty * 4 + (i - 4));
            int m = m0 + row;
            if (m < ROWS_TOT) {
                float* pr = g_parts + ((size_t)ks * ROWS_TOT + m) * 128;
                *reinterpret_cast<unsigned long long*>(pr + tx * 4)          = acc[i][0];
                *reinterpret_cast<unsigned long long*>(pr + tx * 4 + 2)      = acc[i][1];
                *reinterpret_cast<unsigned long long*>(pr + 64 + tx * 4)     = acc[i][2];
                *reinterpret_cast<unsigned long long*>(pr + 64 + tx * 4 + 2) = acc[i][3];
            }
        }
    }
}

// ---------------------------------------------------------------------------
// Kernel 2: reduce partials + tanh -> xe; mask; x_proj = xe@gru_k + b_i;
// rows >= 3200 -> ae.  One CTA per 16 rows (grid 202, clean split at CTA 200).
// ---------------------------------------------------------------------------
__global__ void __launch_bounds__(128) k2_reduce_proj(
    const float* __restrict__ gk, const float* __restrict__ gbi)
{
    __shared__ float xs[16][128];
    __shared__ int nz[16];
    const int tid = threadIdx.x;
    const int r0 = blockIdx.x * 16;

    if (tid < 16) nz[tid] = 0;
    __syncthreads();

    for (int i = tid; i < 16 * 128; i += 128) {
        int r = i >> 7, n = i & 127;
        int m = r0 + r;                       // grid 202*16 = 3232, always valid
        float s = 0.f;
        const float* pp = g_parts + (size_t)m * 128 + n;
        #pragma unroll
        for (int sp = 0; sp < SPLIT; sp++) s += pp[(size_t)sp * ROWS_TOT * 128];
        float v = tanhf(s);
        xs[r][n] = v;
        if (v != 0.f) nz[r] = 1;              // benign race (same value)
    }
    __syncthreads();

    if (r0 < ROWS_X) {
        float acc[16][3];
        #pragma unroll
        for (int r = 0; r < 16; r++) { acc[r][0] = 0.f; acc[r][1] = 0.f; acc[r][2] = 0.f; }
        for (int k = 0; k < 128; k++) {
            float w0 = gk[k * 384 + tid];
            float w1 = gk[k * 384 + 128 + tid];
            float w2 = gk[k * 384 + 256 + tid];
            #pragma unroll
            for (int r = 0; r < 16; r++) {
                float xv = xs[r][k];
                acc[r][0] = fmaf(xv, w0, acc[r][0]);
                acc[r][1] = fmaf(xv, w1, acc[r][1]);
                acc[r][2] = fmaf(xv, w2, acc[r][2]);
            }
        }
        float bb0 = gbi[tid], bb1 = gbi[128 + tid], bb2 = gbi[256 + tid];
        #pragma unroll
        for (int r = 0; r < 16; r++) {
            size_t m = (size_t)(r0 + r);
            g_P[m * 384 + tid]       = acc[r][0] + bb0;
            g_P[m * 384 + 128 + tid] = acc[r][1] + bb1;
            g_P[m * 384 + 256 + tid] = acc[r][2] + bb2;
        }
        if (tid < 16) g_mask[r0 + tid] = nz[tid] ? 1.f : 0.f;
    } else {
        for (int i = tid; i < 16 * 128; i += 128) {
            int r = i >> 7, n = i & 127;
            g_ae[(r0 - ROWS_X + r) * 128 + n] = xs[r][n];
        }
    }
}

// ---------------------------------------------------------------------------
// Kernel 3: per-batch GRU (sequential T=100) + final head. 32 CTAs x 768 thr.
// Recurrent weights register-resident as f32x2 pairs (thread = (j, K-half)).
// ---------------------------------------------------------------------------
__global__ void __launch_bounds__(768, 1) k3_gru(
    const float* __restrict__ grk, const float* __restrict__ gbr,
    const float* __restrict__ dvec, const float* __restrict__ W1,
    const float* __restrict__ b1, const float* __restrict__ W2,
    const float* __restrict__ b2, float* __restrict__ out)
{
    __shared__ float h_s[128];
    __shared__ float rp[2][384];
    __shared__ float xp[2][384];
    __shared__ float msk_s[2];
    __shared__ float cs[64];

    const int tid = threadIdx.x;
    const int b = blockIdx.x;
    const int half = tid / 384;    // 0 or 1 (K halves)
    const int j = tid % 384;       // output column of rec

    // register-resident recurrent weights: 32 k-pairs for column j, half `half`
    unsigned long long wp[32];
    #pragma unroll
    for (int q = 0; q < 32; q++) {
        float w0 = grk[(half * 64 + 2 * q)     * 384 + j];
        float w1 = grk[(half * 64 + 2 * q + 1) * 384 + j];
        asm("mov.b64 %0, {%1, %2};" : "=l"(wp[q]) : "f"(w0), "f"(w1));
    }
    float gz = 0.f, gr = 0.f, gh = 0.f;
    if (tid < 128) { gz = gbr[tid]; gr = gbr[128 + tid]; gh = gbr[256 + tid]; }

    if (tid < 128) h_s[tid] = 0.f;
    if (tid >= 384) { int i = tid - 384; xp[0][i] = g_P[(size_t)(b * T_) * 384 + i]; }
    if (tid == 0) msk_s[0] = g_mask[b * T_];
    __syncthreads();

    for (int t = 0; t < T_; t++) {
        // recurrent partial: rec_half[j] = sum_{k in half} h[k]*grk[k][j]
        unsigned long long acc2 = 0ULL;
        const float* hb = &h_s[half * 64];
        #pragma unroll
        for (int q = 0; q < 32; q++) {
            unsigned long long hp = *reinterpret_cast<const unsigned long long*>(hb + 2 * q);
            asm("fma.rn.f32x2 %0, %1, %2, %0;" : "+l"(acc2) : "l"(hp), "l"(wp[q]));
        }
        float alo, ahi;
        asm("mov.b64 {%0, %1}, %2;" : "=f"(alo), "=f"(ahi) : "l"(acc2));
        rp[half][j] = alo + ahi;

        // prefetch next step's x_proj row + mask (other threads, other buffer)
        if (t + 1 < T_) {
            if (tid >= 384) {
                int i = tid - 384;
                xp[(t + 1) & 1][i] = g_P[(size_t)(b * T_ + t + 1) * 384 + i];
            }
            if (tid == 0) msk_s[(t + 1) & 1] = g_mask[b * T_ + t + 1];
        }
        __syncthreads();

        if (tid < 128) {
            const int jj = tid;
            const float* xpc = xp[t & 1];
            float rz = rp[0][jj]       + rp[1][jj]       + gz;
            float rr = rp[0][jj + 128] + rp[1][jj + 128] + gr;
            float rh = rp[0][jj + 256] + rp[1][jj + 256] + gh;
            float z  = 1.f / (1.f + expf(-(xpc[jj] + rz)));
            float r  = 1.f / (1.f + expf(-(xpc[jj + 128] + rr)));
            float hh = tanhf(xpc[jj + 256] + r * rh);
            float hprev = h_s[jj];
            float hn = z * hprev + (1.f - z) * hh;
            h_s[jj] = (msk_s[t & 1] != 0.f) ? hn : hprev;
        }
        __syncthreads();
    }

    // head: c = tanh([h, ae] @ W1 + b1); out = sigmoid([c, d] @ W2 + b2)
    if (tid < 64) {
        float acc = b1[tid];
        const float* ae = g_ae + b * 128;
        #pragma unroll 4
        for (int k = 0; k < 128; k++) acc = fmaf(h_s[k], W1[k * 64 + tid], acc);
        #pragma unroll 4
        for (int k = 0; k < 128; k++) acc = fmaf(ae[k], W1[(128 + k) * 64 + tid], acc);
        cs[tid] = tanhf(acc) * W2[tid];
    }
    __syncthreads();
    if (tid == 0) {
        float s = 0.f;
        #pragma unroll 8
        for (int i = 0; i < 64; i++) s += cs[i];
        s += dvec[b * 2] * W2[64] + dvec[b * 2 + 1] * W2[65] + b2[0];
        out[b] = 1.f / (1.f + expf(-s));
    }
}

// ---------------------------------------------------------------------------
extern "C" void kernel_launch(void* const* d_in, const int* in_sizes, int n_in,
                              void* d_out, int out_size)
{
    const float* x   = (const float*)d_in[0];
    const float* a   = (const float*)d_in[1];
    const float* dv  = (const float*)d_in[2];
    const float* emb = (const float*)d_in[3];
    const float* gk  = (const float*)d_in[4];
    const float* grk = (const float*)d_in[5];
    const float* gbi = (const float*)d_in[6];
    const float* gbr = (const float*)d_in[7];
    const float* W1  = (const float*)d_in[8];
    const float* b1  = (const float*)d_in[9];
    const float* W2  = (const float*)d_in[10];
    const float* b2  = (const float*)d_in[11];
    float* out = (float*)d_out;

    k1_gemm<<<GRID1, 256>>>(x, a, emb);
    k2_reduce_proj<<<ROWS_TOT / 16, 128>>>(gk, gbi);
    k3_gru<<<B_, 768>>>(grk, gbr, dv, W1, b1, W2, b2, out);
}

// round 4
// speedup vs baseline: 1.7475x; 1.7475x over previous
#include <cuda_runtime.h>
#include <cstdint>

// ------------------------- problem dims -------------------------
#define B_ 32
#define T_ 100
#define V_ 20000
#define E_ 128
#define H_ 128
#define M_ 64
#define ROWS_X (B_*T_)          // 3200
#define ROWS_TOT (ROWS_X + B_)  // 3232

// ------------------------- k1 config ----------------------------
#define CK 64                   // k per chunk (64 bf16 = 128B rows, SW128)
#define NCH 313                 // ceil(20000/64)
#define NRT 26                  // row tiles of 128
#define NSPL 17                 // K splits
#define BASECH 18               // 313 = 7*19 + 10*18
#define EXTRA 7
#define GRID1 (NRT*NSPL)        // 442

// smem: AH[2][16K] AL[2][16K] BH[2][16K] BL[2][16K]
#define OFF_AH 0
#define OFF_AL 32768
#define OFF_BH 65536
#define OFF_BL 98304
#define SMEM_K1 131072

// ------------------------- scratch globals ----------------------
__device__ float    g_parts[(size_t)NSPL * ROWS_TOT * 128];  // 28.1 MB
__device__ uint32_t g_ebh[(size_t)NCH * 4096];               // emb hi, tile-swizzled
__device__ uint32_t g_ebl[(size_t)NCH * 4096];               // emb lo
__device__ float    g_P[(size_t)ROWS_X * 384];
__device__ float    g_mask[ROWS_X];
__device__ float    g_ae[B_ * E_];

// ------------------------- helpers ------------------------------
__device__ __forceinline__ unsigned su32(const void* p) {
    return (unsigned)__cvta_generic_to_shared(p);
}
__device__ __forceinline__ void cpa16(unsigned dst, const void* src) {
    asm volatile("cp.async.ca.shared.global [%0], [%1], 16;\n"
                 :: "r"(dst), "l"(src));
}
__device__ __forceinline__ void ldsm4(uint32_t* r, uint32_t addr) {
    asm volatile("ldmatrix.sync.aligned.m8n8.x4.shared.b16 {%0,%1,%2,%3}, [%4];"
                 : "=r"(r[0]), "=r"(r[1]), "=r"(r[2]), "=r"(r[3]) : "r"(addr));
}
__device__ __forceinline__ void mma16816(float* c, const uint32_t* a, const uint32_t* b) {
    asm volatile("mma.sync.aligned.m16n8k16.row.col.f32.bf16.bf16.f32 "
                 "{%0,%1,%2,%3}, {%4,%5,%6,%7}, {%8,%9}, {%0,%1,%2,%3};"
                 : "+f"(c[0]), "+f"(c[1]), "+f"(c[2]), "+f"(c[3])
                 : "r"(a[0]), "r"(a[1]), "r"(a[2]), "r"(a[3]), "r"(b[0]), "r"(b[1]));
}

// ---------------------------------------------------------------------------
// Kernel 0: emb -> transposed, bf16 hi/lo split, SW128-swizzled 16KB tiles.
// Tile c: [n=0..127 rows][k=0..63 bf16], 128B rows. One CTA per chunk.
// ---------------------------------------------------------------------------
__global__ void __launch_bounds__(256) k0_prep(const float* __restrict__ emb)
{
    __shared__ float se[64][129];   // [kl][n]
    const int c = blockIdx.x, tid = threadIdx.x;

    for (int i = tid; i < 64 * 128; i += 256) {
        int kl = i >> 7, r = i & 127;
        int k = c * CK + kl;
        se[kl][r] = (k < V_) ? emb[(size_t)k * E_ + r] : 0.f;
    }
    __syncthreads();

    uint32_t* oh = g_ebh + (size_t)c * 4096;
    uint32_t* ol = g_ebl + (size_t)c * 4096;
    for (int p = tid; p < 4096; p += 256) {
        uint32_t bo = p * 4;
        uint32_t lg = bo ^ ((bo >> 3) & 0x70);   // swizzle is an involution
        int r = lg >> 7, kl0 = (lg & 127) >> 1;
        float v0 = se[kl0][r], v1 = se[kl0 + 1][r];
        uint32_t hw, lw;
        asm("cvt.rn.bf16x2.f32 %0, %1, %2;" : "=r"(hw) : "f"(v1), "f"(v0));
        float h0 = __uint_as_float(hw << 16);
        float h1 = __uint_as_float(hw & 0xFFFF0000u);
        asm("cvt.rn.bf16x2.f32 %0, %1, %2;" : "=r"(lw) : "f"(v1 - h1), "f"(v0 - h0));
        oh[p] = hw;
        ol[p] = lw;
    }
}

// ---------------------------------------------------------------------------
// Kernel 1: split-bf16 GEMM via ldmatrix + mma.sync (HMMA), split-K partials.
// 512 threads, 16 warps in 4x4 grid, warp tile 32x32.
// ---------------------------------------------------------------------------
__global__ void __launch_bounds__(512, 1) k1_gemm(
    const float* __restrict__ x, const float* __restrict__ a_)
{
    extern __shared__ char smem[];
    const uint32_t sb = su32(smem);
    const int tid = threadIdx.x;
    const int lane = tid & 31;
    const int wid = tid >> 5;
    const int wm = wid >> 2;            // 0..3 (M quarters of 32)
    const int wn = wid & 3;             // 0..3 (N quarters of 32)

    const int rt = blockIdx.x % NRT;
    const int sp = blockIdx.x / NRT;
    const int m0 = rt * 128;
    const int nch = BASECH + (sp < EXTRA ? 1 : 0);
    const int c0  = sp * BASECH + (sp < EXTRA ? sp : EXTRA);

    // ---- loader mapping: thread -> row (tid>>2), 4 float4s ----
    const int arow = tid >> 2;          // 0..127
    const int acol4 = tid & 3;          // float4 id within 16-float group
    const uint32_t xs_a = (uint32_t)(arow & 7) << 4;   // STS swizzle xor

    const float* rowp;
    {
        int m = m0 + arow;
        if (m < ROWS_X)        rowp = x  + (size_t)m * V_;
        else if (m < ROWS_TOT) rowp = a_ + (size_t)(m - ROWS_X) * V_;
        else                   rowp = nullptr;
    }

    // ---- ldmatrix per-lane constants ----
    // A: q = lane>>3: row_off = (q&1)*8 + (lane&7), kboff = (q>>1)*16
    const int aq = lane >> 3;
    const int a_row_off = (aq & 1) * 8 + (lane & 7);
    const uint32_t a_kboff = (uint32_t)(aq >> 1) * 16;
    const uint32_t abase0 = (uint32_t)(wm * 32 + 0 * 16 + a_row_off) * 128;
    const uint32_t abase1 = (uint32_t)(wm * 32 + 1 * 16 + a_row_off) * 128;
    // B: jj = lane>>4, kboff = ((lane>>3)&1)*16
    const int bjj = lane >> 4;
    const uint32_t b_kboff = (uint32_t)((lane >> 3) & 1) * 16;
    const uint32_t bbase0 = (uint32_t)(wn * 32 + 0 * 16 + bjj * 8 + (lane & 7)) * 128;
    const uint32_t bbase1 = (uint32_t)(wn * 32 + 1 * 16 + bjj * 8 + (lane & 7)) * 128;
    const uint32_t xorv = (uint32_t)(lane & 7) << 4;

    float acc[2][4][4];
    #pragma unroll
    for (int i = 0; i < 2; i++)
        #pragma unroll
        for (int j = 0; j < 4; j++)
            #pragma unroll
            for (int q = 0; q < 4; q++) acc[i][j][q] = 0.f;

    float4 av[4];

    // A chunk load: av[q] = x[row][c*64 + q*16 + acol4*4 ..]
    auto loadA = [&](int c) {
        #pragma unroll
        for (int q = 0; q < 4; q++) {
            int kb = c * CK + q * 16 + acol4 * 4;
            av[q] = (rowp && kb < V_) ? *(const float4*)(rowp + kb)
                                      : make_float4(0.f, 0.f, 0.f, 0.f);
        }
    };
    // split av -> bf16 hi/lo, swizzled STS into buffer s
    auto stsA = [&](int s) {
        const uint32_t ah = sb + OFF_AH + s * 16384 + arow * 128;
        const uint32_t al = sb + OFF_AL + s * 16384 + arow * 128;
        #pragma unroll
        for (int q = 0; q < 4; q++) {
            uint32_t ina = ((uint32_t)(q * 32 + acol4 * 8)) ^ xs_a;
            float4 v = av[q];
            uint32_t h0, h1, l0, l1;
            asm("cvt.rn.bf16x2.f32 %0, %1, %2;" : "=r"(h0) : "f"(v.y), "f"(v.x));
            asm("cvt.rn.bf16x2.f32 %0, %1, %2;" : "=r"(h1) : "f"(v.w), "f"(v.z));
            float hx = __uint_as_float(h0 << 16), hy = __uint_as_float(h0 & 0xFFFF0000u);
            float hz = __uint_as_float(h1 << 16), hw_ = __uint_as_float(h1 & 0xFFFF0000u);
            asm("cvt.rn.bf16x2.f32 %0, %1, %2;" : "=r"(l0) : "f"(v.y - hy), "f"(v.x - hx));
            asm("cvt.rn.bf16x2.f32 %0, %1, %2;" : "=r"(l1) : "f"(v.w - hw_), "f"(v.z - hz));
            asm volatile("st.shared.v2.b32 [%0], {%1,%2};" :: "r"(ah + ina), "r"(h0), "r"(h1));
            asm volatile("st.shared.v2.b32 [%0], {%1,%2};" :: "r"(al + ina), "r"(l0), "r"(l1));
        }
    };
    // B tiles via cp.async of pre-swizzled 16KB tiles (verbatim bytes)
    auto cpB = [&](int c, int s) {
        const char* srcH = (const char*)g_ebh + (size_t)c * 16384;
        const char* srcL = (const char*)g_ebl + (size_t)c * 16384;
        const uint32_t bh = sb + OFF_BH + s * 16384;
        const uint32_t bl = sb + OFF_BL + s * 16384;
        #pragma unroll
        for (int j = 0; j < 2; j++) {
            int off = (j * 512 + tid) * 16;
            cpa16(bh + off, srcH + off);
            cpa16(bl + off, srcL + off);
        }
        asm volatile("cp.async.commit_group;");
    };

    // ---- prologue ----
    loadA(c0);
    stsA(0);
    cpB(c0, 0);
    if (nch > 1) loadA(c0 + 1);

    for (int t = 0; t < nch; t++) {
        const int s = t & 1;
        asm volatile("cp.async.wait_group 0;" ::: "memory");
        __syncthreads();   // buf s ready; all warps done reading buf s^1

        if (t + 1 < nch) {
            cpB(c0 + t + 1, s ^ 1);
            stsA(s ^ 1);
            if (t + 2 < nch) loadA(c0 + t + 2);
        }

        const uint32_t ahs = sb + OFF_AH + s * 16384;
        const uint32_t als = sb + OFF_AL + s * 16384;
        const uint32_t bhs = sb + OFF_BH + s * 16384;
        const uint32_t bls = sb + OFF_BL + s * 16384;

        #pragma unroll
        for (int ks = 0; ks < 4; ks++) {
            const uint32_t kta = ((uint32_t)(ks * 32) + a_kboff) ^ xorv;
            const uint32_t ktb = ((uint32_t)(ks * 32) + b_kboff) ^ xorv;
            uint32_t ah0[4], ah1[4], al0[4], al1[4], bh[2][4], bl[2][4];
            ldsm4(ah0, ahs + abase0 + kta);
            ldsm4(ah1, ahs + abase1 + kta);
            ldsm4(al0, als + abase0 + kta);
            ldsm4(al1, als + abase1 + kta);
            ldsm4(bh[0], bhs + bbase0 + ktb);
            ldsm4(bh[1], bhs + bbase1 + ktb);
            ldsm4(bl[0], bls + bbase0 + ktb);
            ldsm4(bl[1], bls + bbase1 + ktb);
            #pragma unroll
            for (int j = 0; j < 4; j++) {
                const uint32_t* bhp = &bh[j >> 1][(j & 1) * 2];
                const uint32_t* blp = &bl[j >> 1][(j & 1) * 2];
                mma16816(acc[0][j], ah0, bhp);
                mma16816(acc[0][j], ah0, blp);
                mma16816(acc[0][j], al0, bhp);
                mma16816(acc[1][j], ah1, bhp);
                mma16816(acc[1][j], ah1, blp);
                mma16816(acc[1][j], al1, bhp);
            }
        }
    }

    // ---- epilogue: write this split's partial tile ----
    const int gid = lane >> 2, tig = lane & 3;
    #pragma unroll
    for (int i = 0; i < 2; i++) {
        int mrow = m0 + wm * 32 + i * 16 + gid;
        #pragma unroll
        for (int j = 0; j < 4; j++) {
            int n = wn * 32 + j * 8 + tig * 2;
            if (mrow < ROWS_TOT) {
                float* d0 = g_parts + ((size_t)sp * ROWS_TOT + mrow) * 128 + n;
                *(float2*)d0 = make_float2(acc[i][j][0], acc[i][j][1]);
            }
            if (mrow + 8 < ROWS_TOT) {
                float* d1 = g_parts + ((size_t)sp * ROWS_TOT + mrow + 8) * 128 + n;
                *(float2*)d1 = make_float2(acc[i][j][2], acc[i][j][3]);
            }
        }
    }
}

// ---------------------------------------------------------------------------
// Kernel 2: reduce partials + tanh -> xe; mask; x_proj = xe@gru_k + b_i;
// rows >= 3200 -> ae.  One CTA per 16 rows.
// ---------------------------------------------------------------------------
__global__ void __launch_bounds__(128) k2_reduce_proj(
    const float* __restrict__ gk, const float* __restrict__ gbi)
{
    __shared__ float xs[16][128];
    __shared__ int nz[16];
    const int tid = threadIdx.x;
    const int r0 = blockIdx.x * 16;

    if (tid < 16) nz[tid] = 0;
    __syncthreads();

    for (int i = tid; i < 16 * 128; i += 128) {
        int r = i >> 7, n = i & 127;
        int m = r0 + r;
        float s = 0.f;
        const float* pp = g_parts + (size_t)m * 128 + n;
        #pragma unroll
        for (int sp = 0; sp < NSPL; sp++) s += pp[(size_t)sp * ROWS_TOT * 128];
        float v = tanhf(s);
        xs[r][n] = v;
        if (v != 0.f) nz[r] = 1;
    }
    __syncthreads();

    if (r0 < ROWS_X) {
        float acc[16][3];
        #pragma unroll
        for (int r = 0; r < 16; r++) { acc[r][0] = 0.f; acc[r][1] = 0.f; acc[r][2] = 0.f; }
        for (int k = 0; k < 128; k++) {
            float w0 = gk[k * 384 + tid];
            float w1 = gk[k * 384 + 128 + tid];
            float w2 = gk[k * 384 + 256 + tid];
            #pragma unroll
            for (int r = 0; r < 16; r++) {
                float xv = xs[r][k];
                acc[r][0] = fmaf(xv, w0, acc[r][0]);
                acc[r][1] = fmaf(xv, w1, acc[r][1]);
                acc[r][2] = fmaf(xv, w2, acc[r][2]);
            }
        }
        float bb0 = gbi[tid], bb1 = gbi[128 + tid], bb2 = gbi[256 + tid];
        #pragma unroll
        for (int r = 0; r < 16; r++) {
            size_t m = (size_t)(r0 + r);
            g_P[m * 384 + tid]       = acc[r][0] + bb0;
            g_P[m * 384 + 128 + tid] = acc[r][1] + bb1;
            g_P[m * 384 + 256 + tid] = acc[r][2] + bb2;
        }
        if (tid < 16) g_mask[r0 + tid] = nz[tid] ? 1.f : 0.f;
    } else {
        for (int i = tid; i < 16 * 128; i += 128) {
            int r = i >> 7, n = i & 127;
            g_ae[(r0 - ROWS_X + r) * 128 + n] = xs[r][n];
        }
    }
}

// ---------------------------------------------------------------------------
// Kernel 3: per-batch GRU (sequential T=100) + final head. 32 CTAs x 768 thr.
// ---------------------------------------------------------------------------
__global__ void __launch_bounds__(768, 1) k3_gru(
    const float* __restrict__ grk, const float* __restrict__ gbr,
    const float* __restrict__ dvec, const float* __restrict__ W1,
    const float* __restrict__ b1, const float* __restrict__ W2,
    const float* __restrict__ b2, float* __restrict__ out)
{
    __shared__ float h_s[128];
    __shared__ float rp[2][384];
    __shared__ float xp[2][384];
    __shared__ float msk_s[2];
    __shared__ float cs[64];

    const int tid = threadIdx.x;
    const int b = blockIdx.x;
    const int half = tid / 384;
    const int j = tid % 384;

    unsigned long long wp[32];
    #pragma unroll
    for (int q = 0; q < 32; q++) {
        float w0 = grk[(half * 64 + 2 * q)     * 384 + j];
        float w1 = grk[(half * 64 + 2 * q + 1) * 384 + j];
        asm("mov.b64 %0, {%1, %2};" : "=l"(wp[q]) : "f"(w0), "f"(w1));
    }
    float gz = 0.f, gr = 0.f, gh = 0.f;
    if (tid < 128) { gz = gbr[tid]; gr = gbr[128 + tid]; gh = gbr[256 + tid]; }

    if (tid < 128) h_s[tid] = 0.f;
    if (tid >= 384) { int i = tid - 384; xp[0][i] = g_P[(size_t)(b * T_) * 384 + i]; }
    if (tid == 0) msk_s[0] = g_mask[b * T_];
    __syncthreads();

    for (int t = 0; t < T_; t++) {
        unsigned long long a0 = 0ULL, a1 = 0ULL, a2 = 0ULL, a3 = 0ULL;
        const float* hb = &h_s[half * 64];
        #pragma unroll
        for (int q = 0; q < 8; q++) {
            unsigned long long hp0 = *reinterpret_cast<const unsigned long long*>(hb + 2 * q);
            unsigned long long hp1 = *reinterpret_cast<const unsigned long long*>(hb + 2 * (q + 8));
            unsigned long long hp2 = *reinterpret_cast<const unsigned long long*>(hb + 2 * (q + 16));
            unsigned long long hp3 = *reinterpret_cast<const unsigned long long*>(hb + 2 * (q + 24));
            asm("fma.rn.f32x2 %0, %1, %2, %0;" : "+l"(a0) : "l"(hp0), "l"(wp[q]));
            asm("fma.rn.f32x2 %0, %1, %2, %0;" : "+l"(a1) : "l"(hp1), "l"(wp[q + 8]));
            asm("fma.rn.f32x2 %0, %1, %2, %0;" : "+l"(a2) : "l"(hp2), "l"(wp[q + 16]));
            asm("fma.rn.f32x2 %0, %1, %2, %0;" : "+l"(a3) : "l"(hp3), "l"(wp[q + 24]));
        }
        float s0, s1, s2, s3, s4, s5, s6, s7;
        asm("mov.b64 {%0, %1}, %2;" : "=f"(s0), "=f"(s1) : "l"(a0));
        asm("mov.b64 {%0, %1}, %2;" : "=f"(s2), "=f"(s3) : "l"(a1));
        asm("mov.b64 {%0, %1}, %2;" : "=f"(s4), "=f"(s5) : "l"(a2));
        asm("mov.b64 {%0, %1}, %2;" : "=f"(s6), "=f"(s7) : "l"(a3));
        rp[half][j] = ((s0 + s1) + (s2 + s3)) + ((s4 + s5) + (s6 + s7));

        if (t + 1 < T_) {
            if (tid >= 384) {
                int i = tid - 384;
                xp[(t + 1) & 1][i] = g_P[(size_t)(b * T_ + t + 1) * 384 + i];
            }
            if (tid == 0) msk_s[(t + 1) & 1] = g_mask[b * T_ + t + 1];
        }
        __syncthreads();

        if (tid < 128) {
            const int jj = tid;
            const float* xpc = xp[t & 1];
            float rz = rp[0][jj]       + rp[1][jj]       + gz;
            float rr = rp[0][jj + 128] + rp[1][jj + 128] + gr;
            float rh = rp[0][jj + 256] + rp[1][jj + 256] + gh;
            float z  = 1.f / (1.f + __expf(-(xpc[jj] + rz)));
            float r  = 1.f / (1.f + __expf(-(xpc[jj + 128] + rr)));
            float hh = tanhf(xpc[jj + 256] + r * rh);
            float hprev = h_s[jj];
            float hn = z * hprev + (1.f - z) * hh;
            h_s[jj] = (msk_s[t & 1] != 0.f) ? hn : hprev;
        }
        __syncthreads();
    }

    if (tid < 64) {
        float acc = b1[tid];
        const float* ae = g_ae + b * 128;
        #pragma unroll 4
        for (int k = 0; k < 128; k++) acc = fmaf(h_s[k], W1[k * 64 + tid], acc);
        #pragma unroll 4
        for (int k = 0; k < 128; k++) acc = fmaf(ae[k], W1[(128 + k) * 64 + tid], acc);
        cs[tid] = tanhf(acc) * W2[tid];
    }
    __syncthreads();
    if (tid == 0) {
        float s = 0.f;
        #pragma unroll 8
        for (int i = 0; i < 64; i++) s += cs[i];
        s += dvec[b * 2] * W2[64] + dvec[b * 2 + 1] * W2[65] + b2[0];
        out[b] = 1.f / (1.f + __expf(-s));
    }
}

// ---------------------------------------------------------------------------
extern "C" void kernel_launch(void* const* d_in, const int* in_sizes, int n_in,
                              void* d_out, int out_size)
{
    const float* x   = (const float*)d_in[0];
    const float* a   = (const float*)d_in[1];
    const float* dv  = (const float*)d_in[2];
    const float* emb = (const float*)d_in[3];
    const float* gk  = (const float*)d_in[4];
    const float* grk = (const float*)d_in[5];
    const float* gbi = (const float*)d_in[6];
    const float* gbr = (const float*)d_in[7];
    const float* W1  = (const float*)d_in[8];
    const float* b1  = (const float*)d_in[9];
    const float* W2  = (const float*)d_in[10];
    const float* b2  = (const float*)d_in[11];
    float* out = (float*)d_out;

    cudaFuncSetAttribute(k1_gemm, cudaFuncAttributeMaxDynamicSharedMemorySize, SMEM_K1);

    k0_prep<<<NCH, 256>>>(emb);
    k1_gemm<<<GRID1, 512, SMEM_K1>>>(x, a);
    k2_reduce_proj<<<ROWS_TOT / 16, 128>>>(gk, gbi);
    k3_gru<<<B_, 768>>>(grk, gbr, dv, W1, b1, W2, b2, out);
}

// round 5
// speedup vs baseline: 1.8947x; 1.0842x over previous
#include <cuda_runtime.h>
#include <cstdint>

// ------------------------- problem dims -------------------------
#define B_ 32
#define T_ 100
#define V_ 20000
#define E_ 128
#define H_ 128
#define M_ 64
#define ROWS_X (B_*T_)          // 3200
#define ROWS_TOT (ROWS_X + B_)  // 3232

// ------------------------- k1 config ----------------------------
#define CK 64                   // k per chunk (64 bf16 = 128B rows, SW128)
#define NCH 313                 // ceil(20000/64)
#define NRT 26                  // row tiles of 128
#define NSPL 17                 // K splits
#define BASECH 18               // 313 = 7*19 + 10*18
#define EXTRA 7
#define GRID1 (NRT*NSPL)        // 442

// smem: AH[2][16K] AL[2][16K] BH[2][16K] BL[2][16K]
#define OFF_AH 0
#define OFF_AL 32768
#define OFF_BH 65536
#define OFF_BL 98304
#define SMEM_K1 131072

// ------------------------- scratch globals ----------------------
__device__ float    g_parts[(size_t)NSPL * ROWS_TOT * 128];  // 28.1 MB
__device__ uint32_t g_ebh[(size_t)NCH * 4096];               // emb hi, tile-swizzled
__device__ uint32_t g_ebl[(size_t)NCH * 4096];               // emb lo
__device__ float    g_P[(size_t)ROWS_X * 384];
__device__ float    g_mask[ROWS_X];
__device__ float    g_ae[B_ * E_];

// ------------------------- helpers ------------------------------
__device__ __forceinline__ unsigned su32(const void* p) {
    return (unsigned)__cvta_generic_to_shared(p);
}
__device__ __forceinline__ void cpa16(unsigned dst, const void* src) {
    asm volatile("cp.async.ca.shared.global [%0], [%1], 16;\n"
                 :: "r"(dst), "l"(src));
}
__device__ __forceinline__ void ldsm4(uint32_t* r, uint32_t addr) {
    asm volatile("ldmatrix.sync.aligned.m8n8.x4.shared.b16 {%0,%1,%2,%3}, [%4];"
                 : "=r"(r[0]), "=r"(r[1]), "=r"(r[2]), "=r"(r[3]) : "r"(addr));
}
__device__ __forceinline__ void mma16816(float* c, const uint32_t* a, const uint32_t* b) {
    asm volatile("mma.sync.aligned.m16n8k16.row.col.f32.bf16.bf16.f32 "
                 "{%0,%1,%2,%3}, {%4,%5,%6,%7}, {%8,%9}, {%0,%1,%2,%3};"
                 : "+f"(c[0]), "+f"(c[1]), "+f"(c[2]), "+f"(c[3])
                 : "r"(a[0]), "r"(a[1]), "r"(a[2]), "r"(a[3]), "r"(b[0]), "r"(b[1]));
}

// fast transcendentals (MUFU-based, err ~2^-22)
#define LOG2E_ 1.4426950408889634f
__device__ __forceinline__ float ex2f(float x) {
    float r; asm("ex2.approx.f32 %0, %1;" : "=f"(r) : "f"(x)); return r;
}
__device__ __forceinline__ float rcpf(float x) {
    float r; asm("rcp.approx.f32 %0, %1;" : "=f"(r) : "f"(x)); return r;
}
__device__ __forceinline__ float sigmoid_f(float v) {
    return rcpf(1.f + ex2f(-v * LOG2E_));
}
__device__ __forceinline__ float tanh_f(float v) {
    return 1.f - 2.f * rcpf(ex2f(2.f * LOG2E_ * v) + 1.f);
}

// ---------------------------------------------------------------------------
// Kernel 0: emb -> transposed, bf16 hi/lo split, SW128-swizzled 16KB tiles.
// ---------------------------------------------------------------------------
__global__ void __launch_bounds__(256) k0_prep(const float* __restrict__ emb)
{
    __shared__ float se[64][129];   // [kl][n]
    const int c = blockIdx.x, tid = threadIdx.x;

    for (int i = tid; i < 64 * 128; i += 256) {
        int kl = i >> 7, r = i & 127;
        int k = c * CK + kl;
        se[kl][r] = (k < V_) ? emb[(size_t)k * E_ + r] : 0.f;
    }
    __syncthreads();

    uint32_t* oh = g_ebh + (size_t)c * 4096;
    uint32_t* ol = g_ebl + (size_t)c * 4096;
    for (int p = tid; p < 4096; p += 256) {
        uint32_t bo = p * 4;
        uint32_t lg = bo ^ ((bo >> 3) & 0x70);   // swizzle is an involution
        int r = lg >> 7, kl0 = (lg & 127) >> 1;
        float v0 = se[kl0][r], v1 = se[kl0 + 1][r];
        uint32_t hw, lw;
        asm("cvt.rn.bf16x2.f32 %0, %1, %2;" : "=r"(hw) : "f"(v1), "f"(v0));
        float h0 = __uint_as_float(hw << 16);
        float h1 = __uint_as_float(hw & 0xFFFF0000u);
        asm("cvt.rn.bf16x2.f32 %0, %1, %2;" : "=r"(lw) : "f"(v1 - h1), "f"(v0 - h0));
        oh[p] = hw;
        ol[p] = lw;
    }
}

// ---------------------------------------------------------------------------
// Kernel 1: split-bf16 GEMM via ldmatrix + mma.sync (HMMA), split-K partials.
// ---------------------------------------------------------------------------
__global__ void __launch_bounds__(512, 1) k1_gemm(
    const float* __restrict__ x, const float* __restrict__ a_)
{
    extern __shared__ char smem[];
    const uint32_t sb = su32(smem);
    const int tid = threadIdx.x;
    const int lane = tid & 31;
    const int wid = tid >> 5;
    const int wm = wid >> 2;
    const int wn = wid & 3;

    const int rt = blockIdx.x % NRT;
    const int sp = blockIdx.x / NRT;
    const int m0 = rt * 128;
    const int nch = BASECH + (sp < EXTRA ? 1 : 0);
    const int c0  = sp * BASECH + (sp < EXTRA ? sp : EXTRA);

    const int arow = tid >> 2;
    const int acol4 = tid & 3;
    const uint32_t xs_a = (uint32_t)(arow & 7) << 4;

    const float* rowp;
    {
        int m = m0 + arow;
        if (m < ROWS_X)        rowp = x  + (size_t)m * V_;
        else if (m < ROWS_TOT) rowp = a_ + (size_t)(m - ROWS_X) * V_;
        else                   rowp = nullptr;
    }

    const int aq = lane >> 3;
    const int a_row_off = (aq & 1) * 8 + (lane & 7);
    const uint32_t a_kboff = (uint32_t)(aq >> 1) * 16;
    const uint32_t abase0 = (uint32_t)(wm * 32 + 0 * 16 + a_row_off) * 128;
    const uint32_t abase1 = (uint32_t)(wm * 32 + 1 * 16 + a_row_off) * 128;
    const int bjj = lane >> 4;
    const uint32_t b_kboff = (uint32_t)((lane >> 3) & 1) * 16;
    const uint32_t bbase0 = (uint32_t)(wn * 32 + 0 * 16 + bjj * 8 + (lane & 7)) * 128;
    const uint32_t bbase1 = (uint32_t)(wn * 32 + 1 * 16 + bjj * 8 + (lane & 7)) * 128;
    const uint32_t xorv = (uint32_t)(lane & 7) << 4;

    float acc[2][4][4];
    #pragma unroll
    for (int i = 0; i < 2; i++)
        #pragma unroll
        for (int j = 0; j < 4; j++)
            #pragma unroll
            for (int q = 0; q < 4; q++) acc[i][j][q] = 0.f;

    float4 av[4];

    auto loadA = [&](int c) {
        #pragma unroll
        for (int q = 0; q < 4; q++) {
            int kb = c * CK + q * 16 + acol4 * 4;
            av[q] = (rowp && kb < V_) ? *(const float4*)(rowp + kb)
                                      : make_float4(0.f, 0.f, 0.f, 0.f);
        }
    };
    auto stsA = [&](int s) {
        const uint32_t ah = sb + OFF_AH + s * 16384 + arow * 128;
        const uint32_t al = sb + OFF_AL + s * 16384 + arow * 128;
        #pragma unroll
        for (int q = 0; q < 4; q++) {
            uint32_t ina = ((uint32_t)(q * 32 + acol4 * 8)) ^ xs_a;
            float4 v = av[q];
            uint32_t h0, h1, l0, l1;
            asm("cvt.rn.bf16x2.f32 %0, %1, %2;" : "=r"(h0) : "f"(v.y), "f"(v.x));
            asm("cvt.rn.bf16x2.f32 %0, %1, %2;" : "=r"(h1) : "f"(v.w), "f"(v.z));
            float hx = __uint_as_float(h0 << 16), hy = __uint_as_float(h0 & 0xFFFF0000u);
            float hz = __uint_as_float(h1 << 16), hw_ = __uint_as_float(h1 & 0xFFFF0000u);
            asm("cvt.rn.bf16x2.f32 %0, %1, %2;" : "=r"(l0) : "f"(v.y - hy), "f"(v.x - hx));
            asm("cvt.rn.bf16x2.f32 %0, %1, %2;" : "=r"(l1) : "f"(v.w - hw_), "f"(v.z - hz));
            asm volatile("st.shared.v2.b32 [%0], {%1,%2};" :: "r"(ah + ina), "r"(h0), "r"(h1));
            asm volatile("st.shared.v2.b32 [%0], {%1,%2};" :: "r"(al + ina), "r"(l0), "r"(l1));
        }
    };
    auto cpB = [&](int c, int s) {
        const char* srcH = (const char*)g_ebh + (size_t)c * 16384;
        const char* srcL = (const char*)g_ebl + (size_t)c * 16384;
        const uint32_t bh = sb + OFF_BH + s * 16384;
        const uint32_t bl = sb + OFF_BL + s * 16384;
        #pragma unroll
        for (int j = 0; j < 2; j++) {
            int off = (j * 512 + tid) * 16;
            cpa16(bh + off, srcH + off);
            cpa16(bl + off, srcL + off);
        }
        asm volatile("cp.async.commit_group;");
    };

    loadA(c0);
    stsA(0);
    cpB(c0, 0);
    if (nch > 1) loadA(c0 + 1);

    for (int t = 0; t < nch; t++) {
        const int s = t & 1;
        asm volatile("cp.async.wait_group 0;" ::: "memory");
        __syncthreads();

        if (t + 1 < nch) {
            cpB(c0 + t + 1, s ^ 1);
            stsA(s ^ 1);
            if (t + 2 < nch) loadA(c0 + t + 2);
        }

        const uint32_t ahs = sb + OFF_AH + s * 16384;
        const uint32_t als = sb + OFF_AL + s * 16384;
        const uint32_t bhs = sb + OFF_BH + s * 16384;
        const uint32_t bls = sb + OFF_BL + s * 16384;

        #pragma unroll
        for (int ks = 0; ks < 4; ks++) {
            const uint32_t kta = ((uint32_t)(ks * 32) + a_kboff) ^ xorv;
            const uint32_t ktb = ((uint32_t)(ks * 32) + b_kboff) ^ xorv;
            uint32_t ah0[4], ah1[4], al0[4], al1[4], bh[2][4], bl[2][4];
            ldsm4(ah0, ahs + abase0 + kta);
            ldsm4(ah1, ahs + abase1 + kta);
            ldsm4(al0, als + abase0 + kta);
            ldsm4(al1, als + abase1 + kta);
            ldsm4(bh[0], bhs + bbase0 + ktb);
            ldsm4(bh[1], bhs + bbase1 + ktb);
            ldsm4(bl[0], bls + bbase0 + ktb);
            ldsm4(bl[1], bls + bbase1 + ktb);
            #pragma unroll
            for (int j = 0; j < 4; j++) {
                const uint32_t* bhp = &bh[j >> 1][(j & 1) * 2];
                const uint32_t* blp = &bl[j >> 1][(j & 1) * 2];
                mma16816(acc[0][j], ah0, bhp);
                mma16816(acc[0][j], ah0, blp);
                mma16816(acc[0][j], al0, bhp);
                mma16816(acc[1][j], ah1, bhp);
                mma16816(acc[1][j], ah1, blp);
                mma16816(acc[1][j], al1, bhp);
            }
        }
    }

    const int gid = lane >> 2, tig = lane & 3;
    #pragma unroll
    for (int i = 0; i < 2; i++) {
        int mrow = m0 + wm * 32 + i * 16 + gid;
        #pragma unroll
        for (int j = 0; j < 4; j++) {
            int n = wn * 32 + j * 8 + tig * 2;
            if (mrow < ROWS_TOT) {
                float* d0 = g_parts + ((size_t)sp * ROWS_TOT + mrow) * 128 + n;
                *(float2*)d0 = make_float2(acc[i][j][0], acc[i][j][1]);
            }
            if (mrow + 8 < ROWS_TOT) {
                float* d1 = g_parts + ((size_t)sp * ROWS_TOT + mrow + 8) * 128 + n;
                *(float2*)d1 = make_float2(acc[i][j][2], acc[i][j][3]);
            }
        }
    }
}

// ---------------------------------------------------------------------------
// Kernel 2: reduce partials + tanh -> xe; mask; x_proj = xe@gru_k + b_i.
// ---------------------------------------------------------------------------
__global__ void __launch_bounds__(128) k2_reduce_proj(
    const float* __restrict__ gk, const float* __restrict__ gbi)
{
    __shared__ float xs[16][128];
    __shared__ int nz[16];
    const int tid = threadIdx.x;
    const int r0 = blockIdx.x * 16;

    if (tid < 16) nz[tid] = 0;
    __syncthreads();

    for (int i = tid; i < 16 * 128; i += 128) {
        int r = i >> 7, n = i & 127;
        int m = r0 + r;
        float s = 0.f;
        const float* pp = g_parts + (size_t)m * 128 + n;
        #pragma unroll
        for (int sp = 0; sp < NSPL; sp++) s += pp[(size_t)sp * ROWS_TOT * 128];
        float v = tanh_f(s);
        xs[r][n] = v;
        if (v != 0.f) nz[r] = 1;
    }
    __syncthreads();

    if (r0 < ROWS_X) {
        float acc[16][3];
        #pragma unroll
        for (int r = 0; r < 16; r++) { acc[r][0] = 0.f; acc[r][1] = 0.f; acc[r][2] = 0.f; }
        for (int k = 0; k < 128; k++) {
            float w0 = gk[k * 384 + tid];
            float w1 = gk[k * 384 + 128 + tid];
            float w2 = gk[k * 384 + 256 + tid];
            #pragma unroll
            for (int r = 0; r < 16; r++) {
                float xv = xs[r][k];
                acc[r][0] = fmaf(xv, w0, acc[r][0]);
                acc[r][1] = fmaf(xv, w1, acc[r][1]);
                acc[r][2] = fmaf(xv, w2, acc[r][2]);
            }
        }
        float bb0 = gbi[tid], bb1 = gbi[128 + tid], bb2 = gbi[256 + tid];
        #pragma unroll
        for (int r = 0; r < 16; r++) {
            size_t m = (size_t)(r0 + r);
            g_P[m * 384 + tid]       = acc[r][0] + bb0;
            g_P[m * 384 + 128 + tid] = acc[r][1] + bb1;
            g_P[m * 384 + 256 + tid] = acc[r][2] + bb2;
        }
        if (tid < 16) g_mask[r0 + tid] = nz[tid] ? 1.f : 0.f;
    } else {
        for (int i = tid; i < 16 * 128; i += 128) {
            int r = i >> 7, n = i & 127;
            g_ae[(r0 - ROWS_X + r) * 128 + n] = xs[r][n];
        }
    }
}

// ---------------------------------------------------------------------------
// Kernel 3 (v2): per-batch GRU + head. 32 CTAs x 384 threads.
// Thread j owns output column j with all 128 recurrent weights in registers
// (64 f32x2). h broadcast via LDS.128. Fast MUFU sigmoid/tanh.
// ---------------------------------------------------------------------------
__global__ void __launch_bounds__(384, 1) k3_gru(
    const float* __restrict__ grk, const float* __restrict__ gbr,
    const float* __restrict__ dvec, const float* __restrict__ W1,
    const float* __restrict__ b1, const float* __restrict__ W2,
    const float* __restrict__ b2, float* __restrict__ out)
{
    __shared__ float h_s[128];
    __shared__ float rp[384];
    __shared__ float xp[2][384];
    __shared__ float msk_s[2];
    __shared__ float cs[64];

    const int tid = threadIdx.x;     // == output column j (0..383)
    const int b = blockIdx.x;

    // register-resident recurrent weights: 64 k-pairs for column tid
    unsigned long long w2[64];
    #pragma unroll
    for (int q = 0; q < 64; q++) {
        float w0 = grk[(2 * q)     * 384 + tid];
        float w1 = grk[(2 * q + 1) * 384 + tid];
        asm("mov.b64 %0, {%1, %2};" : "=l"(w2[q]) : "f"(w0), "f"(w1));
    }
    const float bias = gbr[tid];

    if (tid < 128) h_s[tid] = 0.f;
    xp[0][tid] = g_P[(size_t)(b * T_) * 384 + tid];
    if (tid == 0) msk_s[0] = g_mask[b * T_];
    __syncthreads();

    for (int t = 0; t < T_; t++) {
        // full-K dot: 4 chains over k blocks [0,32) [32,64) [64,96) [96,128)
        unsigned long long a0 = 0ULL, a1 = 0ULL, a2 = 0ULL, a3 = 0ULL;
        #pragma unroll
        for (int q = 0; q < 8; q++) {
            ulonglong2 u0 = *(const ulonglong2*)&h_s[q * 4];
            ulonglong2 u1 = *(const ulonglong2*)&h_s[32 + q * 4];
            ulonglong2 u2 = *(const ulonglong2*)&h_s[64 + q * 4];
            ulonglong2 u3 = *(const ulonglong2*)&h_s[96 + q * 4];
            asm("fma.rn.f32x2 %0, %1, %2, %0;" : "+l"(a0) : "l"(u0.x), "l"(w2[2 * q]));
            asm("fma.rn.f32x2 %0, %1, %2, %0;" : "+l"(a1) : "l"(u1.x), "l"(w2[16 + 2 * q]));
            asm("fma.rn.f32x2 %0, %1, %2, %0;" : "+l"(a2) : "l"(u2.x), "l"(w2[32 + 2 * q]));
            asm("fma.rn.f32x2 %0, %1, %2, %0;" : "+l"(a3) : "l"(u3.x), "l"(w2[48 + 2 * q]));
            asm("fma.rn.f32x2 %0, %1, %2, %0;" : "+l"(a0) : "l"(u0.y), "l"(w2[2 * q + 1]));
            asm("fma.rn.f32x2 %0, %1, %2, %0;" : "+l"(a1) : "l"(u1.y), "l"(w2[16 + 2 * q + 1]));
            asm("fma.rn.f32x2 %0, %1, %2, %0;" : "+l"(a2) : "l"(u2.y), "l"(w2[32 + 2 * q + 1]));
            asm("fma.rn.f32x2 %0, %1, %2, %0;" : "+l"(a3) : "l"(u3.y), "l"(w2[48 + 2 * q + 1]));
        }
        float s0, s1, s2, s3, s4, s5, s6, s7;
        asm("mov.b64 {%0, %1}, %2;" : "=f"(s0), "=f"(s1) : "l"(a0));
        asm("mov.b64 {%0, %1}, %2;" : "=f"(s2), "=f"(s3) : "l"(a1));
        asm("mov.b64 {%0, %1}, %2;" : "=f"(s4), "=f"(s5) : "l"(a2));
        asm("mov.b64 {%0, %1}, %2;" : "=f"(s6), "=f"(s7) : "l"(a3));
        rp[tid] = ((s0 + s1) + (s2 + s3)) + ((s4 + s5) + (s6 + s7)) + bias;

        // prefetch next step's x_proj row + mask
        if (t + 1 < T_) {
            xp[(t + 1) & 1][tid] = g_P[(size_t)(b * T_ + t + 1) * 384 + tid];
            if (tid == 0) msk_s[(t + 1) & 1] = g_mask[b * T_ + t + 1];
        }
        __syncthreads();

        if (tid < 128) {
            const float* xpc = xp[t & 1];
            float rz = rp[tid];
            float rr = rp[tid + 128];
            float rh = rp[tid + 256];
            float z  = sigmoid_f(xpc[tid] + rz);
            float r  = sigmoid_f(xpc[tid + 128] + rr);
            float hh = tanh_f(xpc[tid + 256] + r * rh);
            float hprev = h_s[tid];
            float hn = z * hprev + (1.f - z) * hh;
            h_s[tid] = (msk_s[t & 1] != 0.f) ? hn : hprev;
        }
        __syncthreads();
    }

    // head: c = tanh([h, ae] @ W1 + b1); out = sigmoid([c, d] @ W2 + b2)
    if (tid < 64) {
        float acc = b1[tid];
        const float* ae = g_ae + b * 128;
        #pragma unroll 4
        for (int k = 0; k < 128; k++) acc = fmaf(h_s[k], W1[k * 64 + tid], acc);
        #pragma unroll 4
        for (int k = 0; k < 128; k++) acc = fmaf(ae[k], W1[(128 + k) * 64 + tid], acc);
        cs[tid] = tanh_f(acc) * W2[tid];
    }
    __syncthreads();
    if (tid == 0) {
        float s = 0.f;
        #pragma unroll 8
        for (int i = 0; i < 64; i++) s += cs[i];
        s += dvec[b * 2] * W2[64] + dvec[b * 2 + 1] * W2[65] + b2[0];
        out[b] = sigmoid_f(s);
    }
}

// ---------------------------------------------------------------------------
extern "C" void kernel_launch(void* const* d_in, const int* in_sizes, int n_in,
                              void* d_out, int out_size)
{
    const float* x   = (const float*)d_in[0];
    const float* a   = (const float*)d_in[1];
    const float* dv  = (const float*)d_in[2];
    const float* emb = (const float*)d_in[3];
    const float* gk  = (const float*)d_in[4];
    const float* grk = (const float*)d_in[5];
    const float* gbi = (const float*)d_in[6];
    const float* gbr = (const float*)d_in[7];
    const float* W1  = (const float*)d_in[8];
    const float* b1  = (const float*)d_in[9];
    const float* W2  = (const float*)d_in[10];
    const float* b2  = (const float*)d_in[11];
    float* out = (float*)d_out;

    cudaFuncSetAttribute(k1_gemm, cudaFuncAttributeMaxDynamicSharedMemorySize, SMEM_K1);

    k0_prep<<<NCH, 256>>>(emb);
    k1_gemm<<<GRID1, 512, SMEM_K1>>>(x, a);
    k2_reduce_proj<<<ROWS_TOT / 16, 128>>>(gk, gbi);
    k3_gru<<<B_, 384>>>(grk, gbr, dv, W1, b1, W2, b2, out);
}

// round 6
// speedup vs baseline: 2.0137x; 1.0628x over previous
#include <cuda_runtime.h>
#include <cstdint>

// ------------------------- problem dims -------------------------
#define B_ 32
#define T_ 100
#define V_ 20000
#define E_ 128
#define H_ 128
#define M_ 64
#define ROWS_X (B_*T_)          // 3200
#define ROWS_TOT (ROWS_X + B_)  // 3232

// ------------------------- k1 config ----------------------------
#define CK 64                   // k per chunk (64 bf16 = 128B rows, SW128)
#define NCH 313                 // ceil(20000/64)
#define NRT 26                  // row tiles of 128
#define NSPL 17                 // K splits
#define BASECH 18               // 313 = 7*19 + 10*18
#define EXTRA 7
#define GRID1 (NRT*NSPL)        // 442

// smem: AH[2][16K] AL[2][16K] BH[2][16K] BL[2][16K]
#define OFF_AH 0
#define OFF_AL 32768
#define OFF_BH 65536
#define OFF_BL 98304
#define SMEM_K1 131072

// k3 dynamic smem layout (floats)
#define K3_XP   0                    // [100*384]
#define K3_RP   (K3_XP + T_*384)     // [384]
#define K3_H    (K3_RP + 384)        // [128]
#define K3_MSK  (K3_H + 128)         // [100]
#define K3_CS   (K3_MSK + 100)       // [64]
#define SMEM_K3 ((K3_CS + 64 + 4) * 4)   // ~156.4 KB

// ------------------------- scratch globals ----------------------
__device__ float    g_parts[(size_t)NSPL * ROWS_TOT * 128];  // 28.1 MB
__device__ uint32_t g_ebh[(size_t)NCH * 4096];               // emb hi, tile-swizzled
__device__ uint32_t g_ebl[(size_t)NCH * 4096];               // emb lo
__device__ float    g_P[(size_t)ROWS_X * 384];
__device__ float    g_mask[ROWS_X];
__device__ float    g_ae[B_ * E_];

// ------------------------- helpers ------------------------------
__device__ __forceinline__ unsigned su32(const void* p) {
    return (unsigned)__cvta_generic_to_shared(p);
}
__device__ __forceinline__ void cpa16(unsigned dst, const void* src) {
    asm volatile("cp.async.ca.shared.global [%0], [%1], 16;\n"
                 :: "r"(dst), "l"(src));
}
__device__ __forceinline__ void ldsm4(uint32_t* r, uint32_t addr) {
    asm volatile("ldmatrix.sync.aligned.m8n8.x4.shared.b16 {%0,%1,%2,%3}, [%4];"
                 : "=r"(r[0]), "=r"(r[1]), "=r"(r[2]), "=r"(r[3]) : "r"(addr));
}
__device__ __forceinline__ void mma16816(float* c, const uint32_t* a, const uint32_t* b) {
    asm volatile("mma.sync.aligned.m16n8k16.row.col.f32.bf16.bf16.f32 "
                 "{%0,%1,%2,%3}, {%4,%5,%6,%7}, {%8,%9}, {%0,%1,%2,%3};"
                 : "+f"(c[0]), "+f"(c[1]), "+f"(c[2]), "+f"(c[3])
                 : "r"(a[0]), "r"(a[1]), "r"(a[2]), "r"(a[3]), "r"(b[0]), "r"(b[1]));
}

// fast transcendentals (MUFU-based, err ~2^-22)
#define LOG2E_ 1.4426950408889634f
__device__ __forceinline__ float ex2f(float x) {
    float r; asm("ex2.approx.f32 %0, %1;" : "=f"(r) : "f"(x)); return r;
}
__device__ __forceinline__ float rcpf(float x) {
    float r; asm("rcp.approx.f32 %0, %1;" : "=f"(r) : "f"(x)); return r;
}
__device__ __forceinline__ float sigmoid_f(float v) {
    return rcpf(1.f + ex2f(-v * LOG2E_));
}
__device__ __forceinline__ float tanh_f(float v) {
    return 1.f - 2.f * rcpf(ex2f(2.f * LOG2E_ * v) + 1.f);
}

// ---------------------------------------------------------------------------
// Kernel 0: emb -> transposed, bf16 hi/lo split, SW128-swizzled 16KB tiles.
// ---------------------------------------------------------------------------
__global__ void __launch_bounds__(256) k0_prep(const float* __restrict__ emb)
{
    __shared__ float se[64][129];   // [kl][n]
    const int c = blockIdx.x, tid = threadIdx.x;

    for (int i = tid; i < 64 * 128; i += 256) {
        int kl = i >> 7, r = i & 127;
        int k = c * CK + kl;
        se[kl][r] = (k < V_) ? emb[(size_t)k * E_ + r] : 0.f;
    }
    __syncthreads();

    uint32_t* oh = g_ebh + (size_t)c * 4096;
    uint32_t* ol = g_ebl + (size_t)c * 4096;
    for (int p = tid; p < 4096; p += 256) {
        uint32_t bo = p * 4;
        uint32_t lg = bo ^ ((bo >> 3) & 0x70);   // swizzle is an involution
        int r = lg >> 7, kl0 = (lg & 127) >> 1;
        float v0 = se[kl0][r], v1 = se[kl0 + 1][r];
        uint32_t hw, lw;
        asm("cvt.rn.bf16x2.f32 %0, %1, %2;" : "=r"(hw) : "f"(v1), "f"(v0));
        float h0 = __uint_as_float(hw << 16);
        float h1 = __uint_as_float(hw & 0xFFFF0000u);
        asm("cvt.rn.bf16x2.f32 %0, %1, %2;" : "=r"(lw) : "f"(v1 - h1), "f"(v0 - h0));
        oh[p] = hw;
        ol[p] = lw;
    }
}

// ---------------------------------------------------------------------------
// Kernel 1: split-bf16 GEMM via ldmatrix + mma.sync (HMMA), split-K partials.
// ---------------------------------------------------------------------------
__global__ void __launch_bounds__(512, 1) k1_gemm(
    const float* __restrict__ x, const float* __restrict__ a_)
{
    extern __shared__ char smem[];
    const uint32_t sb = su32(smem);
    const int tid = threadIdx.x;
    const int lane = tid & 31;
    const int wid = tid >> 5;
    const int wm = wid >> 2;
    const int wn = wid & 3;

    const int rt = blockIdx.x % NRT;
    const int sp = blockIdx.x / NRT;
    const int m0 = rt * 128;
    const int nch = BASECH + (sp < EXTRA ? 1 : 0);
    const int c0  = sp * BASECH + (sp < EXTRA ? sp : EXTRA);

    const int arow = tid >> 2;
    const int acol4 = tid & 3;
    const uint32_t xs_a = (uint32_t)(arow & 7) << 4;

    const float* rowp;
    {
        int m = m0 + arow;
        if (m < ROWS_X)        rowp = x  + (size_t)m * V_;
        else if (m < ROWS_TOT) rowp = a_ + (size_t)(m - ROWS_X) * V_;
        else                   rowp = nullptr;
    }

    const int aq = lane >> 3;
    const int a_row_off = (aq & 1) * 8 + (lane & 7);
    const uint32_t a_kboff = (uint32_t)(aq >> 1) * 16;
    const uint32_t abase0 = (uint32_t)(wm * 32 + 0 * 16 + a_row_off) * 128;
    const uint32_t abase1 = (uint32_t)(wm * 32 + 1 * 16 + a_row_off) * 128;
    const int bjj = lane >> 4;
    const uint32_t b_kboff = (uint32_t)((lane >> 3) & 1) * 16;
    const uint32_t bbase0 = (uint32_t)(wn * 32 + 0 * 16 + bjj * 8 + (lane & 7)) * 128;
    const uint32_t bbase1 = (uint32_t)(wn * 32 + 1 * 16 + bjj * 8 + (lane & 7)) * 128;
    const uint32_t xorv = (uint32_t)(lane & 7) << 4;

    float acc[2][4][4];
    #pragma unroll
    for (int i = 0; i < 2; i++)
        #pragma unroll
        for (int j = 0; j < 4; j++)
            #pragma unroll
            for (int q = 0; q < 4; q++) acc[i][j][q] = 0.f;

    float4 av[4];

    auto loadA = [&](int c) {
        #pragma unroll
        for (int q = 0; q < 4; q++) {
            int kb = c * CK + q * 16 + acol4 * 4;
            av[q] = (rowp && kb < V_) ? *(const float4*)(rowp + kb)
                                      : make_float4(0.f, 0.f, 0.f, 0.f);
        }
    };
    auto stsA = [&](int s) {
        const uint32_t ah = sb + OFF_AH + s * 16384 + arow * 128;
        const uint32_t al = sb + OFF_AL + s * 16384 + arow * 128;
        #pragma unroll
        for (int q = 0; q < 4; q++) {
            uint32_t ina = ((uint32_t)(q * 32 + acol4 * 8)) ^ xs_a;
            float4 v = av[q];
            uint32_t h0, h1, l0, l1;
            asm("cvt.rn.bf16x2.f32 %0, %1, %2;" : "=r"(h0) : "f"(v.y), "f"(v.x));
            asm("cvt.rn.bf16x2.f32 %0, %1, %2;" : "=r"(h1) : "f"(v.w), "f"(v.z));
            float hx = __uint_as_float(h0 << 16), hy = __uint_as_float(h0 & 0xFFFF0000u);
            float hz = __uint_as_float(h1 << 16), hw_ = __uint_as_float(h1 & 0xFFFF0000u);
            asm("cvt.rn.bf16x2.f32 %0, %1, %2;" : "=r"(l0) : "f"(v.y - hy), "f"(v.x - hx));
            asm("cvt.rn.bf16x2.f32 %0, %1, %2;" : "=r"(l1) : "f"(v.w - hw_), "f"(v.z - hz));
            asm volatile("st.shared.v2.b32 [%0], {%1,%2};" :: "r"(ah + ina), "r"(h0), "r"(h1));
            asm volatile("st.shared.v2.b32 [%0], {%1,%2};" :: "r"(al + ina), "r"(l0), "r"(l1));
        }
    };
    auto cpB = [&](int c, int s) {
        const char* srcH = (const char*)g_ebh + (size_t)c * 16384;
        const char* srcL = (const char*)g_ebl + (size_t)c * 16384;
        const uint32_t bh = sb + OFF_BH + s * 16384;
        const uint32_t bl = sb + OFF_BL + s * 16384;
        #pragma unroll
        for (int j = 0; j < 2; j++) {
            int off = (j * 512 + tid) * 16;
            cpa16(bh + off, srcH + off);
            cpa16(bl + off, srcL + off);
        }
        asm volatile("cp.async.commit_group;");
    };

    loadA(c0);
    stsA(0);
    cpB(c0, 0);
    if (nch > 1) loadA(c0 + 1);

    for (int t = 0; t < nch; t++) {
        const int s = t & 1;
        asm volatile("cp.async.wait_group 0;" ::: "memory");
        __syncthreads();

        if (t + 1 < nch) {
            cpB(c0 + t + 1, s ^ 1);
            stsA(s ^ 1);
            if (t + 2 < nch) loadA(c0 + t + 2);
        }

        const uint32_t ahs = sb + OFF_AH + s * 16384;
        const uint32_t als = sb + OFF_AL + s * 16384;
        const uint32_t bhs = sb + OFF_BH + s * 16384;
        const uint32_t bls = sb + OFF_BL + s * 16384;

        #pragma unroll
        for (int ks = 0; ks < 4; ks++) {
            const uint32_t kta = ((uint32_t)(ks * 32) + a_kboff) ^ xorv;
            const uint32_t ktb = ((uint32_t)(ks * 32) + b_kboff) ^ xorv;
            uint32_t ah0[4], ah1[4], al0[4], al1[4], bh[2][4], bl[2][4];
            ldsm4(ah0, ahs + abase0 + kta);
            ldsm4(ah1, ahs + abase1 + kta);
            ldsm4(al0, als + abase0 + kta);
            ldsm4(al1, als + abase1 + kta);
            ldsm4(bh[0], bhs + bbase0 + ktb);
            ldsm4(bh[1], bhs + bbase1 + ktb);
            ldsm4(bl[0], bls + bbase0 + ktb);
            ldsm4(bl[1], bls + bbase1 + ktb);
            #pragma unroll
            for (int j = 0; j < 4; j++) {
                const uint32_t* bhp = &bh[j >> 1][(j & 1) * 2];
                const uint32_t* blp = &bl[j >> 1][(j & 1) * 2];
                mma16816(acc[0][j], ah0, bhp);
                mma16816(acc[0][j], ah0, blp);
                mma16816(acc[0][j], al0, bhp);
                mma16816(acc[1][j], ah1, bhp);
                mma16816(acc[1][j], ah1, blp);
                mma16816(acc[1][j], al1, bhp);
            }
        }
    }

    const int gid = lane >> 2, tig = lane & 3;
    #pragma unroll
    for (int i = 0; i < 2; i++) {
        int mrow = m0 + wm * 32 + i * 16 + gid;
        #pragma unroll
        for (int j = 0; j < 4; j++) {
            int n = wn * 32 + j * 8 + tig * 2;
            if (mrow < ROWS_TOT) {
                float* d0 = g_parts + ((size_t)sp * ROWS_TOT + mrow) * 128 + n;
                *(float2*)d0 = make_float2(acc[i][j][0], acc[i][j][1]);
            }
            if (mrow + 8 < ROWS_TOT) {
                float* d1 = g_parts + ((size_t)sp * ROWS_TOT + mrow + 8) * 128 + n;
                *(float2*)d1 = make_float2(acc[i][j][2], acc[i][j][3]);
            }
        }
    }
}

// ---------------------------------------------------------------------------
// Kernel 2: reduce partials + tanh -> xe; mask; x_proj = xe@gru_k + b_i.
// ---------------------------------------------------------------------------
__global__ void __launch_bounds__(128) k2_reduce_proj(
    const float* __restrict__ gk, const float* __restrict__ gbi)
{
    __shared__ float xs[16][128];
    __shared__ int nz[16];
    const int tid = threadIdx.x;
    const int r0 = blockIdx.x * 16;

    if (tid < 16) nz[tid] = 0;
    __syncthreads();

    for (int i = tid; i < 16 * 128; i += 128) {
        int r = i >> 7, n = i & 127;
        int m = r0 + r;
        float s = 0.f;
        const float* pp = g_parts + (size_t)m * 128 + n;
        #pragma unroll
        for (int sp = 0; sp < NSPL; sp++) s += pp[(size_t)sp * ROWS_TOT * 128];
        float v = tanh_f(s);
        xs[r][n] = v;
        if (v != 0.f) nz[r] = 1;
    }
    __syncthreads();

    if (r0 < ROWS_X) {
        float acc[16][3];
        #pragma unroll
        for (int r = 0; r < 16; r++) { acc[r][0] = 0.f; acc[r][1] = 0.f; acc[r][2] = 0.f; }
        for (int k = 0; k < 128; k++) {
            float w0 = gk[k * 384 + tid];
            float w1 = gk[k * 384 + 128 + tid];
            float w2 = gk[k * 384 + 256 + tid];
            #pragma unroll
            for (int r = 0; r < 16; r++) {
                float xv = xs[r][k];
                acc[r][0] = fmaf(xv, w0, acc[r][0]);
                acc[r][1] = fmaf(xv, w1, acc[r][1]);
                acc[r][2] = fmaf(xv, w2, acc[r][2]);
            }
        }
        float bb0 = gbi[tid], bb1 = gbi[128 + tid], bb2 = gbi[256 + tid];
        #pragma unroll
        for (int r = 0; r < 16; r++) {
            size_t m = (size_t)(r0 + r);
            g_P[m * 384 + tid]       = acc[r][0] + bb0;
            g_P[m * 384 + 128 + tid] = acc[r][1] + bb1;
            g_P[m * 384 + 256 + tid] = acc[r][2] + bb2;
        }
        if (tid < 16) g_mask[r0 + tid] = nz[tid] ? 1.f : 0.f;
    } else {
        for (int i = tid; i < 16 * 128; i += 128) {
            int r = i >> 7, n = i & 127;
            g_ae[(r0 - ROWS_X + r) * 128 + n] = xs[r][n];
        }
    }
}

// ---------------------------------------------------------------------------
// Kernel 3 (v3): per-batch GRU + head. 32 CTAs x 384 threads.
// ALL x_proj rows + masks preloaded into dynamic smem (153.6KB) via cp.async
// -> zero global traffic inside the recurrence loop.
// ---------------------------------------------------------------------------
__global__ void __launch_bounds__(384, 1) k3_gru(
    const float* __restrict__ grk, const float* __restrict__ gbr,
    const float* __restrict__ dvec, const float* __restrict__ W1,
    const float* __restrict__ b1, const float* __restrict__ W2,
    const float* __restrict__ b2, float* __restrict__ out)
{
    extern __shared__ float sm3[];
    float* xp  = sm3 + K3_XP;    // [T_*384]
    float* rp  = sm3 + K3_RP;    // [384]
    float* h_s = sm3 + K3_H;     // [128]
    float* msk = sm3 + K3_MSK;   // [100]
    float* cs  = sm3 + K3_CS;    // [64]

    const int tid = threadIdx.x;     // == output column j (0..383)
    const int b = blockIdx.x;

    // bulk preload: 38400 floats of x_proj + 100 mask floats
    {
        const float* src = g_P + (size_t)b * T_ * 384;
        #pragma unroll
        for (int it = 0; it < 25; it++) {
            int i = it * 1536 + tid * 4;         // 384 thr * 4 floats
            cpa16(su32(xp + i), src + i);
        }
        if (tid < 25) cpa16(su32(msk + tid * 4), g_mask + b * T_ + tid * 4);
        asm volatile("cp.async.commit_group;");
    }

    // register-resident recurrent weights: 64 k-pairs for column tid
    unsigned long long w2[64];
    #pragma unroll
    for (int q = 0; q < 64; q++) {
        float w0 = grk[(2 * q)     * 384 + tid];
        float w1 = grk[(2 * q + 1) * 384 + tid];
        asm("mov.b64 %0, {%1, %2};" : "=l"(w2[q]) : "f"(w0), "f"(w1));
    }
    const float bias = gbr[tid];

    if (tid < 128) h_s[tid] = 0.f;
    asm volatile("cp.async.wait_group 0;" ::: "memory");
    __syncthreads();

    for (int t = 0; t < T_; t++) {
        // full-K dot: 4 chains over k blocks [0,32) [32,64) [64,96) [96,128)
        unsigned long long a0 = 0ULL, a1 = 0ULL, a2 = 0ULL, a3 = 0ULL;
        #pragma unroll
        for (int q = 0; q < 8; q++) {
            ulonglong2 u0 = *(const ulonglong2*)&h_s[q * 4];
            ulonglong2 u1 = *(const ulonglong2*)&h_s[32 + q * 4];
            ulonglong2 u2 = *(const ulonglong2*)&h_s[64 + q * 4];
            ulonglong2 u3 = *(const ulonglong2*)&h_s[96 + q * 4];
            asm("fma.rn.f32x2 %0, %1, %2, %0;" : "+l"(a0) : "l"(u0.x), "l"(w2[2 * q]));
            asm("fma.rn.f32x2 %0, %1, %2, %0;" : "+l"(a1) : "l"(u1.x), "l"(w2[16 + 2 * q]));
            asm("fma.rn.f32x2 %0, %1, %2, %0;" : "+l"(a2) : "l"(u2.x), "l"(w2[32 + 2 * q]));
            asm("fma.rn.f32x2 %0, %1, %2, %0;" : "+l"(a3) : "l"(u3.x), "l"(w2[48 + 2 * q]));
            asm("fma.rn.f32x2 %0, %1, %2, %0;" : "+l"(a0) : "l"(u0.y), "l"(w2[2 * q + 1]));
            asm("fma.rn.f32x2 %0, %1, %2, %0;" : "+l"(a1) : "l"(u1.y), "l"(w2[16 + 2 * q + 1]));
            asm("fma.rn.f32x2 %0, %1, %2, %0;" : "+l"(a2) : "l"(u2.y), "l"(w2[32 + 2 * q + 1]));
            asm("fma.rn.f32x2 %0, %1, %2, %0;" : "+l"(a3) : "l"(u3.y), "l"(w2[48 + 2 * q + 1]));
        }
        float s0, s1, s2, s3, s4, s5, s6, s7;
        asm("mov.b64 {%0, %1}, %2;" : "=f"(s0), "=f"(s1) : "l"(a0));
        asm("mov.b64 {%0, %1}, %2;" : "=f"(s2), "=f"(s3) : "l"(a1));
        asm("mov.b64 {%0, %1}, %2;" : "=f"(s4), "=f"(s5) : "l"(a2));
        asm("mov.b64 {%0, %1}, %2;" : "=f"(s6), "=f"(s7) : "l"(a3));
        rp[tid] = ((s0 + s1) + (s2 + s3)) + ((s4 + s5) + (s6 + s7)) + bias;
        __syncthreads();

        if (tid < 128) {
            const float* xpc = xp + t * 384;
            float z  = sigmoid_f(xpc[tid] + rp[tid]);
            float r  = sigmoid_f(xpc[tid + 128] + rp[tid + 128]);
            float hh = tanh_f(xpc[tid + 256] + r * rp[tid + 256]);
            float hprev = h_s[tid];
            float hn = z * hprev + (1.f - z) * hh;
            h_s[tid] = (msk[t] != 0.f) ? hn : hprev;
        }
        __syncthreads();
    }

    // head: c = tanh([h, ae] @ W1 + b1); out = sigmoid([c, d] @ W2 + b2)
    if (tid < 64) {
        float acc = b1[tid];
        const float* ae = g_ae + b * 128;
        #pragma unroll 4
        for (int k = 0; k < 128; k++) acc = fmaf(h_s[k], W1[k * 64 + tid], acc);
        #pragma unroll 4
        for (int k = 0; k < 128; k++) acc = fmaf(ae[k], W1[(128 + k) * 64 + tid], acc);
        cs[tid] = tanh_f(acc) * W2[tid];
    }
    __syncthreads();
    if (tid == 0) {
        float s = 0.f;
        #pragma unroll 8
        for (int i = 0; i < 64; i++) s += cs[i];
        s += dvec[b * 2] * W2[64] + dvec[b * 2 + 1] * W2[65] + b2[0];
        out[b] = sigmoid_f(s);
    }
}

// ---------------------------------------------------------------------------
extern "C" void kernel_launch(void* const* d_in, const int* in_sizes, int n_in,
                              void* d_out, int out_size)
{
    const float* x   = (const float*)d_in[0];
    const float* a   = (const float*)d_in[1];
    const float* dv  = (const float*)d_in[2];
    const float* emb = (const float*)d_in[3];
    const float* gk  = (const float*)d_in[4];
    const float* grk = (const float*)d_in[5];
    const float* gbi = (const float*)d_in[6];
    const float* gbr = (const float*)d_in[7];
    const float* W1  = (const float*)d_in[8];
    const float* b1  = (const float*)d_in[9];
    const float* W2  = (const float*)d_in[10];
    const float* b2  = (const float*)d_in[11];
    float* out = (float*)d_out;

    cudaFuncSetAttribute(k1_gemm, cudaFuncAttributeMaxDynamicSharedMemorySize, SMEM_K1);
    cudaFuncSetAttribute(k3_gru,  cudaFuncAttributeMaxDynamicSharedMemorySize, SMEM_K3);

    k0_prep<<<NCH, 256>>>(emb);
    k1_gemm<<<GRID1, 512, SMEM_K1>>>(x, a);
    k2_reduce_proj<<<ROWS_TOT / 16, 128>>>(gk, gbi);
    k3_gru<<<B_, 384, SMEM_K3>>>(grk, gbr, dv, W1, b1, W2, b2, out);
}